// round 15
// baseline (speedup 1.0000x reference)
#include <cuda_runtime.h>
#include <cuda_fp16.h>
#include <cstdint>

#define Bq 2
#define Sq 2048
#define Hq 8
#define DEPTHq 64
#define DMq 512
#define NTOK (Bq * Sq)
#define NROWS (2 * NTOK)
#define CC 1536
#define BHq (Bq * Hq)

// ---------------- device scratch ----------------
__device__ __half g_Ch[NROWS * CC];
__device__ __half g_Ah[NROWS * DMq];
__device__ __half g_Wth[CC * DMq];
__device__ __half g_Woth[DMq * DMq];
__device__ __half g_Qh[BHq * Sq * 128];
__device__ __half g_Kh[BHq * Sq * 128];
__device__ __half g_Vh[BHq * Sq * DEPTHq];
__device__ __half g_attn_h[(size_t)BHq * Sq * Sq];
__device__ __half g_Zh[NTOK * DMq];
__device__ float  g_rowsum[BHq * Sq];
__device__ float  g_attn_fallback[(size_t)BHq * Sq * Sq];

// ---------------- helpers ----------------
__device__ __forceinline__ uint32_t ph2(float a, float b) {
    __half2 h = __floats2half2_rn(a, b);
    return *reinterpret_cast<uint32_t*>(&h);
}
__device__ __forceinline__ void mma16(float* c, const uint32_t* a, const uint32_t* b) {
    asm volatile(
        "mma.sync.aligned.m16n8k16.row.col.f32.f16.f16.f32 "
        "{%0,%1,%2,%3}, {%4,%5,%6,%7}, {%8,%9}, {%0,%1,%2,%3};"
        : "+f"(c[0]), "+f"(c[1]), "+f"(c[2]), "+f"(c[3])
        : "r"(a[0]), "r"(a[1]), "r"(a[2]), "r"(a[3]),
          "r"(b[0]), "r"(b[1]));
}
__device__ __forceinline__ uint32_t smem_u32(const void* p) {
    uint32_t a;
    asm("{ .reg .u64 t; cvta.to.shared.u64 t, %1; cvt.u32.u64 %0, t; }" : "=r"(a) : "l"(p));
    return a;
}
__device__ __forceinline__ void cp16(uint32_t dst, const void* src) {
    asm volatile("cp.async.ca.shared.global [%0], [%1], 16;" :: "r"(dst), "l"(src));
}
__device__ __forceinline__ void ldsm4(uint32_t* r, uint32_t addr) {
    asm volatile("ldmatrix.sync.aligned.m8n8.x4.shared.b16 {%0,%1,%2,%3}, [%4];"
                 : "=r"(r[0]), "=r"(r[1]), "=r"(r[2]), "=r"(r[3]) : "r"(addr));
}

// ============================================================
// Kernel 0a: convert [emb;pe] -> fp16
// ============================================================
__global__ void convert_A(const float* __restrict__ emb, const float* __restrict__ pe) {
    int idx = blockIdx.x * 256 + threadIdx.x;
    if (idx >= NROWS * DMq) return;
    float v = (idx < NTOK * DMq) ? emb[idx] : pe[idx - NTOK * DMq];
    g_Ah[idx] = __float2half_rn(v);
}

// ============================================================
// Kernel 0b/0c: weight transposes
// ============================================================
__global__ void convert_W(const float* __restrict__ Wq, const float* __restrict__ Wk,
                          const float* __restrict__ Wv) {
    __shared__ __half t[32][33];
    const int bn = blockIdx.x * 32;
    const int bk = blockIdx.y * 32;
    const int tx = threadIdx.x, ty = threadIdx.y;
    const float* W = (bn < 512) ? Wq : (bn < 1024 ? Wk : Wv);
    const int colbase = bn & 511;
#pragma unroll
    for (int i = 0; i < 32; i += 8)
        t[ty + i][tx] = __float2half_rn(W[(size_t)(bk + ty + i) * DMq + colbase + tx]);
    __syncthreads();
#pragma unroll
    for (int i = 0; i < 32; i += 8)
        g_Wth[(size_t)(bn + ty + i) * DMq + bk + tx] = t[tx][ty + i];
}

__global__ void convert_Wo(const float* __restrict__ Wo) {
    __shared__ __half t[32][33];
    const int bn = blockIdx.x * 32;
    const int bk = blockIdx.y * 32;
    const int tx = threadIdx.x, ty = threadIdx.y;
#pragma unroll
    for (int i = 0; i < 32; i += 8)
        t[ty + i][tx] = __float2half_rn(Wo[(size_t)(bk + ty + i) * DMq + bn + tx]);
    __syncthreads();
#pragma unroll
    for (int i = 0; i < 32; i += 8)
        g_Woth[(size_t)(bn + ty + i) * DMq + bk + tx] = t[tx][ty + i];
}

// ============================================================
// Shared GEMM template constants
// ============================================================
#define PROWB 144
#define PSTG (128 * PROWB)
#define PROJ_SMEM (4 * PSTG)

// ============================================================
// Kernel 1: proj (R14 design)
// ============================================================
__global__ void __launch_bounds__(256)
proj_gemm_v2(const float* __restrict__ bq, const float* __restrict__ bk,
             const float* __restrict__ bv) {
    extern __shared__ char dsm[];
    const uint32_t sa = smem_u32(dsm);
    const uint32_t sb = sa + 2 * PSTG;

    const int m0 = blockIdx.y * 128;
    const int n0 = blockIdx.x * 128;
    const int tid = threadIdx.x;
    const int wid = tid >> 5, lane = tid & 31;
    const int wm = (wid >> 2) * 64, wn = (wid & 3) * 32;
    const int lg = lane >> 2, lt = lane & 3;

    const float* bias = (n0 < 512) ? bq : (n0 < 1024 ? bk : bv);

    const int crow = tid >> 3;
    const int ccc = tid & 7;

    float acc[4][4][4];
#pragma unroll
    for (int i = 0; i < 4; i++)
#pragma unroll
        for (int j = 0; j < 4; j++)
#pragma unroll
            for (int r = 0; r < 4; r++) acc[i][j][r] = 0.f;

    {
#pragma unroll
        for (int i = 0; i < 4; i++) {
            int row = crow + i * 32;
            cp16(sa + row * PROWB + ccc * 16, g_Ah + (size_t)(m0 + row) * DMq + ccc * 8);
            cp16(sb + row * PROWB + ccc * 16, g_Wth + (size_t)(n0 + row) * DMq + ccc * 8);
        }
        asm volatile("cp.async.commit_group;" ::: "memory");
        asm volatile("cp.async.wait_group 0;" ::: "memory");
    }
    __syncthreads();

    const uint32_t aAddrBase = (uint32_t)(wm + (lane & 15)) * PROWB + ((lane >> 4) & 1) * 16;
    const uint32_t bAddrBase = (uint32_t)(wn + ((lane >> 4) & 1) * 8 + (lane & 7)) * PROWB +
                               ((lane >> 3) & 1) * 16;

    const int NST = DMq / 64;
    for (int s = 0; s < NST; s++) {
        const int st = s & 1;
        const bool more = (s + 1 < NST);
        if (more) {
            int k0 = (s + 1) * 64;
#pragma unroll
            for (int i = 0; i < 4; i++) {
                int row = crow + i * 32;
                cp16(sa + (st ^ 1) * PSTG + row * PROWB + ccc * 16,
                     g_Ah + (size_t)(m0 + row) * DMq + k0 + ccc * 8);
                cp16(sb + (st ^ 1) * PSTG + row * PROWB + ccc * 16,
                     g_Wth + (size_t)(n0 + row) * DMq + k0 + ccc * 8);
            }
            asm volatile("cp.async.commit_group;" ::: "memory");
        }
        const uint32_t sas = sa + st * PSTG;
        const uint32_t sbs = sb + st * PSTG;
#pragma unroll
        for (int c = 0; c < 4; c++) {
            const uint32_t coff = c * 32;
            uint32_t bf[4][2];
#pragma unroll
            for (int np = 0; np < 2; np++) {
                uint32_t r4[4];
                ldsm4(r4, sbs + bAddrBase + np * 16 * PROWB + coff);
                bf[2 * np][0] = r4[0];
                bf[2 * np][1] = r4[1];
                bf[2 * np + 1][0] = r4[2];
                bf[2 * np + 1][1] = r4[3];
            }
#pragma unroll
            for (int mi = 0; mi < 4; mi++) {
                uint32_t af[4];
                ldsm4(af, sas + aAddrBase + mi * 16 * PROWB + coff);
#pragma unroll
                for (int ni = 0; ni < 4; ni++) mma16(acc[mi][ni], af, bf[ni]);
            }
        }
        if (more) asm volatile("cp.async.wait_group 0;" ::: "memory");
        __syncthreads();
    }

#pragma unroll
    for (int mi = 0; mi < 4; mi++) {
        int r0 = m0 + wm + mi * 16 + lg;
#pragma unroll
        for (int ni = 0; ni < 4; ni++) {
            int c0 = n0 + wn + ni * 8 + 2 * lt;
            float bv0 = bias[(c0) & 511], bv1 = bias[(c0 + 1) & 511];
            *reinterpret_cast<uint32_t*>(&g_Ch[(size_t)r0 * CC + c0]) =
                ph2(acc[mi][ni][0] + bv0, acc[mi][ni][1] + bv1);
            *reinterpret_cast<uint32_t*>(&g_Ch[(size_t)(r0 + 8) * CC + c0]) =
                ph2(acc[mi][ni][2] + bv0, acc[mi][ni][3] + bv1);
        }
    }
}

// ============================================================
// Kernel 2: rearrange (R14 design)
// ============================================================
__global__ void rearrange_kernel() {
    int idx = blockIdx.x * blockDim.x + threadIdx.x;
    if (idx >= NTOK * (DMq / 2)) return;
    int n = idx / (DMq / 2);
    int c = (idx % (DMq / 2)) * 2;
    int b = n / Sq, s = n % Sq;
    int h = c / DEPTHq, d = c % DEPTHq;

    float2 qc = __half22float2(*(const __half2*)&g_Ch[(size_t)n * CC + c]);
    float2 qr = __half22float2(*(const __half2*)&g_Ch[(size_t)(NTOK + n) * CC + c]);
    __half2 kc = *(const __half2*)&g_Ch[(size_t)n * CC + 512 + c];
    __half2 kr = *(const __half2*)&g_Ch[(size_t)(NTOK + n) * CC + 512 + c];
    __half2 vv = *(const __half2*)&g_Ch[(size_t)n * CC + 1024 + c];

    size_t base = ((size_t)(b * Hq + h) * Sq + s) * 128;
    *reinterpret_cast<uint32_t*>(&g_Qh[base + d]) =
        ph2((qc.x + qr.x) * 0.125f, (qc.y + qr.y) * 0.125f);
    *reinterpret_cast<uint32_t*>(&g_Qh[base + 64 + d]) =
        ph2(qc.x * 0.125f, qc.y * 0.125f);
    *(__half2*)&g_Kh[base + d] = kc;
    *(__half2*)&g_Kh[base + 64 + d] = kr;
    *(__half2*)&g_Vh[((size_t)(b * Hq + h) * Sq + s) * DEPTHq + d] = vv;
}

__global__ void zero_rowsum() {
    int i = blockIdx.x * 256 + threadIdx.x;
    if (i < BHq * Sq) g_rowsum[i] = 0.f;
}

// ============================================================
// Kernel 3 (NEW): logits — 256 threads, 8 warps (2x4) of 64x32,
// whole-tile-resident (same smem as R10), higher occupancy.
// ============================================================
#define ROWB 272
#define LOG_SMEM (2 * 128 * ROWB)

__global__ void __launch_bounds__(256)
logits_gemm_tc() {
    extern __shared__ char dsm[];
    const uint32_t sa = smem_u32(dsm);
    const uint32_t sb = sa + 128 * ROWB;

    const int bh = blockIdx.z;
    const int q0 = blockIdx.y * 128;
    const int t0 = blockIdx.x * 128;
    const __half* Q = g_Qh + (size_t)bh * Sq * 128;
    const __half* K = g_Kh + (size_t)bh * Sq * 128;
    __half* outh = g_attn_h + (size_t)bh * Sq * Sq;

    const int tid = threadIdx.x;
    const int wid = tid >> 5, lane = tid & 31;
    const int wm = (wid >> 2) * 64, wn = (wid & 3) * 32;
    const int lg = lane >> 2, lt = lane & 3;

    // prologue: cp.async full tiles (8 chunks per thread)
    {
        const int cr = tid >> 4;     // 0..15
        const int cc = tid & 15;     // 0..15
#pragma unroll
        for (int i = 0; i < 8; i++) {
            int row = i * 16 + cr;
            cp16(sa + row * ROWB + cc * 16, Q + (size_t)(q0 + row) * 128 + cc * 8);
            cp16(sb + row * ROWB + cc * 16, K + (size_t)(t0 + row) * 128 + cc * 8);
        }
        asm volatile("cp.async.commit_group;" ::: "memory");
        asm volatile("cp.async.wait_group 0;" ::: "memory");
    }
    __syncthreads();

    float acc[4][4][4];
#pragma unroll
    for (int i = 0; i < 4; i++)
#pragma unroll
        for (int j = 0; j < 4; j++)
#pragma unroll
            for (int r = 0; r < 4; r++) acc[i][j][r] = 0.f;

    const uint32_t aAddrBase = sa + (uint32_t)(wm + (lane & 15)) * ROWB + ((lane >> 4) & 1) * 16;
    const uint32_t bAddrBase = sb + (uint32_t)(wn + ((lane >> 4) & 1) * 8 + (lane & 7)) * ROWB +
                               ((lane >> 3) & 1) * 16;

#pragma unroll
    for (int c = 0; c < 8; c++) {
        const uint32_t coff = c * 32;
        uint32_t bf[4][2];
#pragma unroll
        for (int np = 0; np < 2; np++) {
            uint32_t r4[4];
            ldsm4(r4, bAddrBase + np * 16 * ROWB + coff);
            bf[2 * np][0] = r4[0];
            bf[2 * np][1] = r4[1];
            bf[2 * np + 1][0] = r4[2];
            bf[2 * np + 1][1] = r4[3];
        }
#pragma unroll
        for (int mi = 0; mi < 4; mi++) {
            uint32_t af[4];
            ldsm4(af, aAddrBase + mi * 16 * ROWB + coff);
#pragma unroll
            for (int ni = 0; ni < 4; ni++) mma16(acc[mi][ni], af, bf[ni]);
        }
    }

    // epilogue: exp -> fp16 store + rowsum
#pragma unroll
    for (int mi = 0; mi < 4; mi++) {
        int r0 = q0 + wm + mi * 16 + lg;
        float rs0 = 0.f, rs1 = 0.f;
#pragma unroll
        for (int ni = 0; ni < 4; ni++) {
            int c0 = t0 + wn + ni * 8 + 2 * lt;
            __half2 h01 = __floats2half2_rn(__expf(acc[mi][ni][0]), __expf(acc[mi][ni][1]));
            __half2 h23 = __floats2half2_rn(__expf(acc[mi][ni][2]), __expf(acc[mi][ni][3]));
            *reinterpret_cast<uint32_t*>(&outh[(size_t)r0 * Sq + c0]) =
                *reinterpret_cast<uint32_t*>(&h01);
            *reinterpret_cast<uint32_t*>(&outh[(size_t)(r0 + 8) * Sq + c0]) =
                *reinterpret_cast<uint32_t*>(&h23);
            float2 f01 = __half22float2(h01);
            float2 f23 = __half22float2(h23);
            rs0 += f01.x + f01.y;
            rs1 += f23.x + f23.y;
        }
        rs0 += __shfl_xor_sync(0xffffffffu, rs0, 1);
        rs0 += __shfl_xor_sync(0xffffffffu, rs0, 2);
        rs1 += __shfl_xor_sync(0xffffffffu, rs1, 1);
        rs1 += __shfl_xor_sync(0xffffffffu, rs1, 2);
        if (lt == 0) {
            atomicAdd(&g_rowsum[bh * Sq + r0], rs0);
            atomicAdd(&g_rowsum[bh * Sq + r0 + 8], rs1);
        }
    }
}

// ============================================================
// Kernel 5: zv (R13 design, unchanged)
// ============================================================
#define AROWB 48
#define ZASTG (128 * AROWB)

__global__ void __launch_bounds__(256, 2)
zv_fused_tc(float* __restrict__ attn) {
    __shared__ __align__(16) char  ZA[2 * ZASTG];
    __shared__ __align__(16) uint32_t SB[2][64][8];

    const int bh = blockIdx.y;
    const int q0 = blockIdx.x * 128;
    const int b = bh / Hq, h = bh % Hq;
    const __half* Ph = g_attn_h + (size_t)bh * Sq * Sq;
    float* Pout = attn + (size_t)bh * Sq * Sq;
    const __half* V = g_Vh + (size_t)bh * Sq * DEPTHq;

    const int tid = threadIdx.x;
    const int wid = tid >> 5, lane = tid & 31;
    const int wm = (wid >> 1) * 32, wn = (wid & 1) * 32;
    const int lg = lane >> 2, lt = lane & 3;

    const uint32_t za = smem_u32(ZA);

    const int arow = tid >> 1, ahalf = tid & 1;
    const __half* agsrc = Ph + (size_t)(q0 + arow) * Sq + ahalf * 8;
    float* aout = Pout + (size_t)(q0 + arow) * Sq + ahalf * 8;
    const uint32_t adst = za + arow * AROWB + ahalf * 16;
    const float invs = 1.0f / g_rowsum[bh * Sq + q0 + arow];

    const int kp = tid >> 5, bn_ = (tid & 31) * 2;
    const int slot = (kp < 4) ? 2 * kp : 2 * (kp - 4) + 1;

    const uint32_t aAddrBase = za + (uint32_t)(wm + (lane & 15)) * AROWB + ((lane >> 4) & 1) * 16;

    float acc[2][4][4];
#pragma unroll
    for (int i = 0; i < 2; i++)
#pragma unroll
        for (int j = 0; j < 4; j++)
#pragma unroll
            for (int r = 0; r < 4; r++) acc[i][j][r] = 0.f;

    const int NIT = Sq / 16;

    {
        cp16(adst, agsrc);
        asm volatile("cp.async.commit_group;" ::: "memory");
        const __half* vp = V + (size_t)(2 * kp) * DEPTHq + bn_;
        uint32_t x0 = *(const uint32_t*)vp;
        uint32_t x1 = *(const uint32_t*)(vp + DEPTHq);
        SB[0][bn_][slot]     = __byte_perm(x0, x1, 0x5410);
        SB[0][bn_ + 1][slot] = __byte_perm(x0, x1, 0x7632);
        asm volatile("cp.async.wait_group 0;" ::: "memory");
    }
    __syncthreads();

    for (int it = 0; it < NIT; it++) {
        const int st = it & 1;
        const bool more = (it + 1 < NIT);
        uint32_t x0, x1;
        if (more) {
            int k0 = (it + 1) * 16;
            cp16(adst + (st ^ 1) * ZASTG, agsrc + k0);
            asm volatile("cp.async.commit_group;" ::: "memory");
            const __half* vp = V + (size_t)(k0 + 2 * kp) * DEPTHq + bn_;
            x0 = *(const uint32_t*)vp;
            x1 = *(const uint32_t*)(vp + DEPTHq);
        }

        {
            uint4 u = *reinterpret_cast<const uint4*>(ZA + st * ZASTG + arow * AROWB + ahalf * 16);
            float2 p0 = __half22float2(*reinterpret_cast<__half2*>(&u.x));
            float2 p1 = __half22float2(*reinterpret_cast<__half2*>(&u.y));
            float2 p2 = __half22float2(*reinterpret_cast<__half2*>(&u.z));
            float2 p3 = __half22float2(*reinterpret_cast<__half2*>(&u.w));
            *(float4*)(aout + it * 16)     = make_float4(p0.x * invs, p0.y * invs, p1.x * invs, p1.y * invs);
            *(float4*)(aout + it * 16 + 4) = make_float4(p2.x * invs, p2.y * invs, p3.x * invs, p3.y * invs);
        }

        {
            uint32_t af[2][4], bf[4][2];
#pragma unroll
            for (int mi = 0; mi < 2; mi++)
                ldsm4(af[mi], aAddrBase + st * ZASTG + mi * 16 * AROWB);
#pragma unroll
            for (int ni = 0; ni < 4; ni++) {
                uint2 bb = *(const uint2*)&SB[st][wn + ni * 8 + lg][2 * lt];
                bf[ni][0] = bb.x; bf[ni][1] = bb.y;
            }
#pragma unroll
            for (int mi = 0; mi < 2; mi++)
#pragma unroll
                for (int ni = 0; ni < 4; ni++) mma16(acc[mi][ni], af[mi], bf[ni]);
        }

        if (more) {
            SB[st ^ 1][bn_][slot]     = __byte_perm(x0, x1, 0x5410);
            SB[st ^ 1][bn_ + 1][slot] = __byte_perm(x0, x1, 0x7632);
            asm volatile("cp.async.wait_group 0;" ::: "memory");
        }
        __syncthreads();
    }

#pragma unroll
    for (int mi = 0; mi < 2; mi++) {
        int r0 = q0 + wm + mi * 16 + lg;
        float iv0 = 1.0f / g_rowsum[bh * Sq + r0];
        float iv1 = 1.0f / g_rowsum[bh * Sq + r0 + 8];
#pragma unroll
        for (int ni = 0; ni < 4; ni++) {
            int c0 = wn + ni * 8 + 2 * lt;
            size_t base0 = ((size_t)b * Sq + r0) * DMq + h * DEPTHq + c0;
            size_t base1 = ((size_t)b * Sq + r0 + 8) * DMq + h * DEPTHq + c0;
            *reinterpret_cast<uint32_t*>(&g_Zh[base0]) =
                ph2(acc[mi][ni][0] * iv0, acc[mi][ni][1] * iv0);
            *reinterpret_cast<uint32_t*>(&g_Zh[base1]) =
                ph2(acc[mi][ni][2] * iv1, acc[mi][ni][3] * iv1);
        }
    }
}

// ============================================================
// Kernel 6: out (R13 design, unchanged)
// ============================================================
__global__ void __launch_bounds__(256)
out_gemm_v2(const float* __restrict__ bo, float* __restrict__ out) {
    extern __shared__ char dsm[];
    const uint32_t sa = smem_u32(dsm);
    const uint32_t sb = sa + 2 * PSTG;

    const int m0 = blockIdx.y * 128;
    const int n0 = blockIdx.x * 128;
    const int tid = threadIdx.x;
    const int wid = tid >> 5, lane = tid & 31;
    const int wm = (wid >> 2) * 64, wn = (wid & 3) * 32;
    const int lg = lane >> 2, lt = lane & 3;

    const int crow = tid >> 3;
    const int ccc = tid & 7;

    float acc[4][4][4];
#pragma unroll
    for (int i = 0; i < 4; i++)
#pragma unroll
        for (int j = 0; j < 4; j++)
#pragma unroll
            for (int r = 0; r < 4; r++) acc[i][j][r] = 0.f;

    {
#pragma unroll
        for (int i = 0; i < 4; i++) {
            int row = crow + i * 32;
            cp16(sa + row * PROWB + ccc * 16, g_Zh + (size_t)(m0 + row) * DMq + ccc * 8);
            cp16(sb + row * PROWB + ccc * 16, g_Woth + (size_t)(n0 + row) * DMq + ccc * 8);
        }
        asm volatile("cp.async.commit_group;" ::: "memory");
        asm volatile("cp.async.wait_group 0;" ::: "memory");
    }
    __syncthreads();

    const uint32_t aAddrBase = (uint32_t)(wm + (lane & 15)) * PROWB + ((lane >> 4) & 1) * 16;
    const uint32_t bAddrBase = (uint32_t)(wn + ((lane >> 4) & 1) * 8 + (lane & 7)) * PROWB +
                               ((lane >> 3) & 1) * 16;

    const int NST = DMq / 64;
    for (int s = 0; s < NST; s++) {
        const int st = s & 1;
        const bool more = (s + 1 < NST);
        if (more) {
            int k0 = (s + 1) * 64;
#pragma unroll
            for (int i = 0; i < 4; i++) {
                int row = crow + i * 32;
                cp16(sa + (st ^ 1) * PSTG + row * PROWB + ccc * 16,
                     g_Zh + (size_t)(m0 + row) * DMq + k0 + ccc * 8);
                cp16(sb + (st ^ 1) * PSTG + row * PROWB + ccc * 16,
                     g_Woth + (size_t)(n0 + row) * DMq + k0 + ccc * 8);
            }
            asm volatile("cp.async.commit_group;" ::: "memory");
        }
        const uint32_t sas = sa + st * PSTG;
        const uint32_t sbs = sb + st * PSTG;
#pragma unroll
        for (int c = 0; c < 4; c++) {
            const uint32_t coff = c * 32;
            uint32_t bf[4][2];
#pragma unroll
            for (int np = 0; np < 2; np++) {
                uint32_t r4[4];
                ldsm4(r4, sbs + bAddrBase + np * 16 * PROWB + coff);
                bf[2 * np][0] = r4[0];
                bf[2 * np][1] = r4[1];
                bf[2 * np + 1][0] = r4[2];
                bf[2 * np + 1][1] = r4[3];
            }
#pragma unroll
            for (int mi = 0; mi < 4; mi++) {
                uint32_t af[4];
                ldsm4(af, sas + aAddrBase + mi * 16 * PROWB + coff);
#pragma unroll
                for (int ni = 0; ni < 4; ni++) mma16(acc[mi][ni], af, bf[ni]);
            }
        }
        if (more) asm volatile("cp.async.wait_group 0;" ::: "memory");
        __syncthreads();
    }

#pragma unroll
    for (int mi = 0; mi < 4; mi++) {
        int r0 = m0 + wm + mi * 16 + lg;
#pragma unroll
        for (int ni = 0; ni < 4; ni++) {
            int c0 = n0 + wn + ni * 8 + 2 * lt;
            float bv0 = bo[c0], bv1 = bo[c0 + 1];
            *reinterpret_cast<float2*>(&out[(size_t)r0 * DMq + c0]) =
                make_float2(acc[mi][ni][0] + bv0, acc[mi][ni][1] + bv1);
            *reinterpret_cast<float2*>(&out[(size_t)(r0 + 8) * DMq + c0]) =
                make_float2(acc[mi][ni][2] + bv0, acc[mi][ni][3] + bv1);
        }
    }
}

// ============================================================
// Launch
// ============================================================
extern "C" void kernel_launch(void* const* d_in, const int* in_sizes, int n_in,
                              void* d_out, int out_size) {
    const float* emb = (const float*)d_in[0];
    const float* pe  = (const float*)d_in[1];
    const float* Wq  = (const float*)d_in[2];
    const float* bq  = (const float*)d_in[3];
    const float* Wk  = (const float*)d_in[4];
    const float* bk  = (const float*)d_in[5];
    const float* Wv  = (const float*)d_in[6];
    const float* bv  = (const float*)d_in[7];
    const float* Wo  = (const float*)d_in[8];
    const float* bo  = (const float*)d_in[9];

    float* out = (float*)d_out;

    const long long need = (long long)NTOK * DMq + (long long)BHq * Sq * Sq;
    float* attn;
    if ((long long)out_size >= need) {
        attn = out + (size_t)NTOK * DMq;
    } else {
        float* p = nullptr;
        cudaGetSymbolAddress((void**)&p, g_attn_fallback);
        attn = p;
    }

    cudaFuncSetAttribute(logits_gemm_tc,
                         cudaFuncAttributeMaxDynamicSharedMemorySize, LOG_SMEM);
    cudaFuncSetAttribute(proj_gemm_v2,
                         cudaFuncAttributeMaxDynamicSharedMemorySize, PROJ_SMEM);
    cudaFuncSetAttribute(out_gemm_v2,
                         cudaFuncAttributeMaxDynamicSharedMemorySize, PROJ_SMEM);

    {
        convert_A<<<(NROWS * DMq + 255) / 256, 256>>>(emb, pe);
    }
    {
        dim3 grid(CC / 32, DMq / 32);
        convert_W<<<grid, dim3(32, 8)>>>(Wq, Wk, Wv);
    }
    {
        dim3 grid(DMq / 32, DMq / 32);
        convert_Wo<<<grid, dim3(32, 8)>>>(Wo);
    }
    {
        dim3 grid(CC / 128, NROWS / 128);
        proj_gemm_v2<<<grid, 256, PROJ_SMEM>>>(bq, bk, bv);
    }
    {
        int total = NTOK * (DMq / 2);
        rearrange_kernel<<<(total + 255) / 256, 256>>>();
    }
    {
        zero_rowsum<<<(BHq * Sq + 255) / 256, 256>>>();
    }
    {
        dim3 grid(Sq / 128, Sq / 128, BHq);
        logits_gemm_tc<<<grid, 256, LOG_SMEM>>>();
    }
    {
        dim3 grid(Sq / 128, BHq);
        zv_fused_tc<<<grid, 256>>>(attn);
    }
    {
        dim3 grid(DMq / 128, NTOK / 128);
        out_gemm_v2<<<grid, 256, PROJ_SMEM>>>(bo, out);
    }
}

// round 16
// speedup vs baseline: 1.0097x; 1.0097x over previous
#include <cuda_runtime.h>
#include <cuda_fp16.h>
#include <cstdint>

#define Bq 2
#define Sq 2048
#define Hq 8
#define DEPTHq 64
#define DMq 512
#define NTOK (Bq * Sq)
#define NROWS (2 * NTOK)
#define CC 1536
#define BHq (Bq * Hq)

// ---------------- device scratch ----------------
__device__ __half g_Ch[NROWS * CC];
__device__ __half g_Ah[NROWS * DMq];
__device__ __half g_Wth[CC * DMq];
__device__ __half g_Woth[DMq * DMq];
__device__ __half g_Qh[BHq * Sq * 128];
__device__ __half g_Kh[BHq * Sq * 128];
__device__ __half g_Vh[BHq * Sq * DEPTHq];
__device__ __half g_attn_h[(size_t)BHq * Sq * Sq];
__device__ __half g_Zh[NTOK * DMq];
__device__ float  g_rowsum[BHq * Sq];
__device__ float  g_attn_fallback[(size_t)BHq * Sq * Sq];

// ---------------- helpers ----------------
__device__ __forceinline__ uint32_t ph2(float a, float b) {
    __half2 h = __floats2half2_rn(a, b);
    return *reinterpret_cast<uint32_t*>(&h);
}
__device__ __forceinline__ void mma16(float* c, const uint32_t* a, const uint32_t* b) {
    asm volatile(
        "mma.sync.aligned.m16n8k16.row.col.f32.f16.f16.f32 "
        "{%0,%1,%2,%3}, {%4,%5,%6,%7}, {%8,%9}, {%0,%1,%2,%3};"
        : "+f"(c[0]), "+f"(c[1]), "+f"(c[2]), "+f"(c[3])
        : "r"(a[0]), "r"(a[1]), "r"(a[2]), "r"(a[3]),
          "r"(b[0]), "r"(b[1]));
}
__device__ __forceinline__ uint32_t smem_u32(const void* p) {
    uint32_t a;
    asm("{ .reg .u64 t; cvta.to.shared.u64 t, %1; cvt.u32.u64 %0, t; }" : "=r"(a) : "l"(p));
    return a;
}
__device__ __forceinline__ void cp16(uint32_t dst, const void* src) {
    asm volatile("cp.async.ca.shared.global [%0], [%1], 16;" :: "r"(dst), "l"(src));
}
__device__ __forceinline__ void ldsm4(uint32_t* r, uint32_t addr) {
    asm volatile("ldmatrix.sync.aligned.m8n8.x4.shared.b16 {%0,%1,%2,%3}, [%4];"
                 : "=r"(r[0]), "=r"(r[1]), "=r"(r[2]), "=r"(r[3]) : "r"(addr));
}

// ============================================================
// Kernel 0a: convert [emb;pe] -> fp16 (+ zero rowsum)
// ============================================================
__global__ void convert_A(const float* __restrict__ emb, const float* __restrict__ pe) {
    int idx = blockIdx.x * 256 + threadIdx.x;
    if (idx < BHq * Sq) g_rowsum[idx] = 0.f;
    if (idx >= NROWS * DMq) return;
    float v = (idx < NTOK * DMq) ? emb[idx] : pe[idx - NTOK * DMq];
    g_Ah[idx] = __float2half_rn(v);
}

// ============================================================
// Kernel 0b: convert + transpose ALL weights (Wq|Wk|Wv and Wo)
// grid.x covers CC/32 (QKV) + DMq/32 (Wo) tiles.
// ============================================================
__global__ void convert_W_all(const float* __restrict__ Wq, const float* __restrict__ Wk,
                              const float* __restrict__ Wv, const float* __restrict__ Wo) {
    __shared__ __half t[32][33];
    const int bx = blockIdx.x;
    const int bk = blockIdx.y * 32;
    const int tx = threadIdx.x, ty = threadIdx.y;
    if (bx < CC / 32) {
        const int bn = bx * 32;
        const float* W = (bn < 512) ? Wq : (bn < 1024 ? Wk : Wv);
        const int colbase = bn & 511;
#pragma unroll
        for (int i = 0; i < 32; i += 8)
            t[ty + i][tx] = __float2half_rn(W[(size_t)(bk + ty + i) * DMq + colbase + tx]);
        __syncthreads();
#pragma unroll
        for (int i = 0; i < 32; i += 8)
            g_Wth[(size_t)(bn + ty + i) * DMq + bk + tx] = t[tx][ty + i];
    } else {
        const int bn = (bx - CC / 32) * 32;
#pragma unroll
        for (int i = 0; i < 32; i += 8)
            t[ty + i][tx] = __float2half_rn(Wo[(size_t)(bk + ty + i) * DMq + bn + tx]);
        __syncthreads();
#pragma unroll
        for (int i = 0; i < 32; i += 8)
            g_Woth[(size_t)(bn + ty + i) * DMq + bk + tx] = t[tx][ty + i];
    }
}

// ============================================================
// Shared GEMM template constants
// ============================================================
#define PROWB 144
#define PSTG (128 * PROWB)
#define PROJ_SMEM (4 * PSTG)

// ============================================================
// Kernel 1: proj (R14 design, unchanged)
// ============================================================
__global__ void __launch_bounds__(256)
proj_gemm_v2(const float* __restrict__ bq, const float* __restrict__ bk,
             const float* __restrict__ bv) {
    extern __shared__ char dsm[];
    const uint32_t sa = smem_u32(dsm);
    const uint32_t sb = sa + 2 * PSTG;

    const int m0 = blockIdx.y * 128;
    const int n0 = blockIdx.x * 128;
    const int tid = threadIdx.x;
    const int wid = tid >> 5, lane = tid & 31;
    const int wm = (wid >> 2) * 64, wn = (wid & 3) * 32;
    const int lg = lane >> 2, lt = lane & 3;

    const float* bias = (n0 < 512) ? bq : (n0 < 1024 ? bk : bv);

    const int crow = tid >> 3;
    const int ccc = tid & 7;

    float acc[4][4][4];
#pragma unroll
    for (int i = 0; i < 4; i++)
#pragma unroll
        for (int j = 0; j < 4; j++)
#pragma unroll
            for (int r = 0; r < 4; r++) acc[i][j][r] = 0.f;

    {
#pragma unroll
        for (int i = 0; i < 4; i++) {
            int row = crow + i * 32;
            cp16(sa + row * PROWB + ccc * 16, g_Ah + (size_t)(m0 + row) * DMq + ccc * 8);
            cp16(sb + row * PROWB + ccc * 16, g_Wth + (size_t)(n0 + row) * DMq + ccc * 8);
        }
        asm volatile("cp.async.commit_group;" ::: "memory");
        asm volatile("cp.async.wait_group 0;" ::: "memory");
    }
    __syncthreads();

    const uint32_t aAddrBase = (uint32_t)(wm + (lane & 15)) * PROWB + ((lane >> 4) & 1) * 16;
    const uint32_t bAddrBase = (uint32_t)(wn + ((lane >> 4) & 1) * 8 + (lane & 7)) * PROWB +
                               ((lane >> 3) & 1) * 16;

    const int NST = DMq / 64;
    for (int s = 0; s < NST; s++) {
        const int st = s & 1;
        const bool more = (s + 1 < NST);
        if (more) {
            int k0 = (s + 1) * 64;
#pragma unroll
            for (int i = 0; i < 4; i++) {
                int row = crow + i * 32;
                cp16(sa + (st ^ 1) * PSTG + row * PROWB + ccc * 16,
                     g_Ah + (size_t)(m0 + row) * DMq + k0 + ccc * 8);
                cp16(sb + (st ^ 1) * PSTG + row * PROWB + ccc * 16,
                     g_Wth + (size_t)(n0 + row) * DMq + k0 + ccc * 8);
            }
            asm volatile("cp.async.commit_group;" ::: "memory");
        }
        const uint32_t sas = sa + st * PSTG;
        const uint32_t sbs = sb + st * PSTG;
#pragma unroll
        for (int c = 0; c < 4; c++) {
            const uint32_t coff = c * 32;
            uint32_t bf[4][2];
#pragma unroll
            for (int np = 0; np < 2; np++) {
                uint32_t r4[4];
                ldsm4(r4, sbs + bAddrBase + np * 16 * PROWB + coff);
                bf[2 * np][0] = r4[0];
                bf[2 * np][1] = r4[1];
                bf[2 * np + 1][0] = r4[2];
                bf[2 * np + 1][1] = r4[3];
            }
#pragma unroll
            for (int mi = 0; mi < 4; mi++) {
                uint32_t af[4];
                ldsm4(af, sas + aAddrBase + mi * 16 * PROWB + coff);
#pragma unroll
                for (int ni = 0; ni < 4; ni++) mma16(acc[mi][ni], af, bf[ni]);
            }
        }
        if (more) asm volatile("cp.async.wait_group 0;" ::: "memory");
        __syncthreads();
    }

#pragma unroll
    for (int mi = 0; mi < 4; mi++) {
        int r0 = m0 + wm + mi * 16 + lg;
#pragma unroll
        for (int ni = 0; ni < 4; ni++) {
            int c0 = n0 + wn + ni * 8 + 2 * lt;
            float bv0 = bias[(c0) & 511], bv1 = bias[(c0 + 1) & 511];
            *reinterpret_cast<uint32_t*>(&g_Ch[(size_t)r0 * CC + c0]) =
                ph2(acc[mi][ni][0] + bv0, acc[mi][ni][1] + bv1);
            *reinterpret_cast<uint32_t*>(&g_Ch[(size_t)(r0 + 8) * CC + c0]) =
                ph2(acc[mi][ni][2] + bv0, acc[mi][ni][3] + bv1);
        }
    }
}

// ============================================================
// Kernel 2: rearrange (R14 design, unchanged)
// ============================================================
__global__ void rearrange_kernel() {
    int idx = blockIdx.x * blockDim.x + threadIdx.x;
    if (idx >= NTOK * (DMq / 2)) return;
    int n = idx / (DMq / 2);
    int c = (idx % (DMq / 2)) * 2;
    int b = n / Sq, s = n % Sq;
    int h = c / DEPTHq, d = c % DEPTHq;

    float2 qc = __half22float2(*(const __half2*)&g_Ch[(size_t)n * CC + c]);
    float2 qr = __half22float2(*(const __half2*)&g_Ch[(size_t)(NTOK + n) * CC + c]);
    __half2 kc = *(const __half2*)&g_Ch[(size_t)n * CC + 512 + c];
    __half2 kr = *(const __half2*)&g_Ch[(size_t)(NTOK + n) * CC + 512 + c];
    __half2 vv = *(const __half2*)&g_Ch[(size_t)n * CC + 1024 + c];

    size_t base = ((size_t)(b * Hq + h) * Sq + s) * 128;
    *reinterpret_cast<uint32_t*>(&g_Qh[base + d]) =
        ph2((qc.x + qr.x) * 0.125f, (qc.y + qr.y) * 0.125f);
    *reinterpret_cast<uint32_t*>(&g_Qh[base + 64 + d]) =
        ph2(qc.x * 0.125f, qc.y * 0.125f);
    *(__half2*)&g_Kh[base + d] = kc;
    *(__half2*)&g_Kh[base + 64 + d] = kr;
    *(__half2*)&g_Vh[((size_t)(b * Hq + h) * Sq + s) * DEPTHq + d] = vv;
}

// ============================================================
// Kernel 3: logits (R10 design — 128 thr, 4 warps of 64x64)
// ============================================================
#define ROWB 272
#define LOG_SMEM (2 * 128 * ROWB)

__global__ void __launch_bounds__(128)
logits_gemm_tc() {
    extern __shared__ char dsm[];
    const uint32_t sa = smem_u32(dsm);
    const uint32_t sb = sa + 128 * ROWB;

    const int bh = blockIdx.z;
    const int q0 = blockIdx.y * 128;
    const int t0 = blockIdx.x * 128;
    const __half* Q = g_Qh + (size_t)bh * Sq * 128;
    const __half* K = g_Kh + (size_t)bh * Sq * 128;
    __half* outh = g_attn_h + (size_t)bh * Sq * Sq;

    const int tid = threadIdx.x;
    const int wid = tid >> 5, lane = tid & 31;
    const int wm = (wid >> 1) * 64, wn = (wid & 1) * 64;
    const int lg = lane >> 2, lt = lane & 3;

    {
        const int cr = tid >> 4;
        const int cc = tid & 15;
#pragma unroll
        for (int i = 0; i < 16; i++) {
            int row = i * 8 + cr;
            cp16(sa + row * ROWB + cc * 16, Q + (size_t)(q0 + row) * 128 + cc * 8);
            cp16(sb + row * ROWB + cc * 16, K + (size_t)(t0 + row) * 128 + cc * 8);
        }
        asm volatile("cp.async.commit_group;" ::: "memory");
        asm volatile("cp.async.wait_group 0;" ::: "memory");
    }
    __syncthreads();

    float acc[4][8][4];
#pragma unroll
    for (int i = 0; i < 4; i++)
#pragma unroll
        for (int j = 0; j < 8; j++)
#pragma unroll
            for (int r = 0; r < 4; r++) acc[i][j][r] = 0.f;

    const uint32_t aAddrBase = sa + (uint32_t)(wm + (lane & 15)) * ROWB + ((lane >> 4) & 1) * 16;
    const uint32_t bAddrBase = sb + (uint32_t)(wn + ((lane >> 4) & 1) * 8 + (lane & 7)) * ROWB +
                               ((lane >> 3) & 1) * 16;

#pragma unroll
    for (int c = 0; c < 8; c++) {
        const uint32_t coff = c * 32;
        uint32_t bf[8][2];
#pragma unroll
        for (int np = 0; np < 4; np++) {
            uint32_t r4[4];
            ldsm4(r4, bAddrBase + np * 16 * ROWB + coff);
            bf[2 * np][0] = r4[0];
            bf[2 * np][1] = r4[1];
            bf[2 * np + 1][0] = r4[2];
            bf[2 * np + 1][1] = r4[3];
        }
#pragma unroll
        for (int mi = 0; mi < 4; mi++) {
            uint32_t af[4];
            ldsm4(af, aAddrBase + mi * 16 * ROWB + coff);
#pragma unroll
            for (int ni = 0; ni < 8; ni++) mma16(acc[mi][ni], af, bf[ni]);
        }
    }

#pragma unroll
    for (int mi = 0; mi < 4; mi++) {
        int r0 = q0 + wm + mi * 16 + lg;
        float rs0 = 0.f, rs1 = 0.f;
#pragma unroll
        for (int ni = 0; ni < 8; ni++) {
            int c0 = t0 + wn + ni * 8 + 2 * lt;
            __half2 h01 = __floats2half2_rn(__expf(acc[mi][ni][0]), __expf(acc[mi][ni][1]));
            __half2 h23 = __floats2half2_rn(__expf(acc[mi][ni][2]), __expf(acc[mi][ni][3]));
            *reinterpret_cast<uint32_t*>(&outh[(size_t)r0 * Sq + c0]) =
                *reinterpret_cast<uint32_t*>(&h01);
            *reinterpret_cast<uint32_t*>(&outh[(size_t)(r0 + 8) * Sq + c0]) =
                *reinterpret_cast<uint32_t*>(&h23);
            float2 f01 = __half22float2(h01);
            float2 f23 = __half22float2(h23);
            rs0 += f01.x + f01.y;
            rs1 += f23.x + f23.y;
        }
        rs0 += __shfl_xor_sync(0xffffffffu, rs0, 1);
        rs0 += __shfl_xor_sync(0xffffffffu, rs0, 2);
        rs1 += __shfl_xor_sync(0xffffffffu, rs1, 1);
        rs1 += __shfl_xor_sync(0xffffffffu, rs1, 2);
        if (lt == 0) {
            atomicAdd(&g_rowsum[bh * Sq + r0], rs0);
            atomicAdd(&g_rowsum[bh * Sq + r0 + 8], rs1);
        }
    }
}

// ============================================================
// Kernel 5: zv (R13 design, unchanged)
// ============================================================
#define AROWB 48
#define ZASTG (128 * AROWB)

__global__ void __launch_bounds__(256, 2)
zv_fused_tc(float* __restrict__ attn) {
    __shared__ __align__(16) char  ZA[2 * ZASTG];
    __shared__ __align__(16) uint32_t SB[2][64][8];

    const int bh = blockIdx.y;
    const int q0 = blockIdx.x * 128;
    const int b = bh / Hq, h = bh % Hq;
    const __half* Ph = g_attn_h + (size_t)bh * Sq * Sq;
    float* Pout = attn + (size_t)bh * Sq * Sq;
    const __half* V = g_Vh + (size_t)bh * Sq * DEPTHq;

    const int tid = threadIdx.x;
    const int wid = tid >> 5, lane = tid & 31;
    const int wm = (wid >> 1) * 32, wn = (wid & 1) * 32;
    const int lg = lane >> 2, lt = lane & 3;

    const uint32_t za = smem_u32(ZA);

    const int arow = tid >> 1, ahalf = tid & 1;
    const __half* agsrc = Ph + (size_t)(q0 + arow) * Sq + ahalf * 8;
    float* aout = Pout + (size_t)(q0 + arow) * Sq + ahalf * 8;
    const uint32_t adst = za + arow * AROWB + ahalf * 16;
    const float invs = 1.0f / g_rowsum[bh * Sq + q0 + arow];

    const int kp = tid >> 5, bn_ = (tid & 31) * 2;
    const int slot = (kp < 4) ? 2 * kp : 2 * (kp - 4) + 1;

    const uint32_t aAddrBase = za + (uint32_t)(wm + (lane & 15)) * AROWB + ((lane >> 4) & 1) * 16;

    float acc[2][4][4];
#pragma unroll
    for (int i = 0; i < 2; i++)
#pragma unroll
        for (int j = 0; j < 4; j++)
#pragma unroll
            for (int r = 0; r < 4; r++) acc[i][j][r] = 0.f;

    const int NIT = Sq / 16;

    {
        cp16(adst, agsrc);
        asm volatile("cp.async.commit_group;" ::: "memory");
        const __half* vp = V + (size_t)(2 * kp) * DEPTHq + bn_;
        uint32_t x0 = *(const uint32_t*)vp;
        uint32_t x1 = *(const uint32_t*)(vp + DEPTHq);
        SB[0][bn_][slot]     = __byte_perm(x0, x1, 0x5410);
        SB[0][bn_ + 1][slot] = __byte_perm(x0, x1, 0x7632);
        asm volatile("cp.async.wait_group 0;" ::: "memory");
    }
    __syncthreads();

    for (int it = 0; it < NIT; it++) {
        const int st = it & 1;
        const bool more = (it + 1 < NIT);
        uint32_t x0, x1;
        if (more) {
            int k0 = (it + 1) * 16;
            cp16(adst + (st ^ 1) * ZASTG, agsrc + k0);
            asm volatile("cp.async.commit_group;" ::: "memory");
            const __half* vp = V + (size_t)(k0 + 2 * kp) * DEPTHq + bn_;
            x0 = *(const uint32_t*)vp;
            x1 = *(const uint32_t*)(vp + DEPTHq);
        }

        {
            uint4 u = *reinterpret_cast<const uint4*>(ZA + st * ZASTG + arow * AROWB + ahalf * 16);
            float2 p0 = __half22float2(*reinterpret_cast<__half2*>(&u.x));
            float2 p1 = __half22float2(*reinterpret_cast<__half2*>(&u.y));
            float2 p2 = __half22float2(*reinterpret_cast<__half2*>(&u.z));
            float2 p3 = __half22float2(*reinterpret_cast<__half2*>(&u.w));
            *(float4*)(aout + it * 16)     = make_float4(p0.x * invs, p0.y * invs, p1.x * invs, p1.y * invs);
            *(float4*)(aout + it * 16 + 4) = make_float4(p2.x * invs, p2.y * invs, p3.x * invs, p3.y * invs);
        }

        {
            uint32_t af[2][4], bf[4][2];
#pragma unroll
            for (int mi = 0; mi < 2; mi++)
                ldsm4(af[mi], aAddrBase + st * ZASTG + mi * 16 * AROWB);
#pragma unroll
            for (int ni = 0; ni < 4; ni++) {
                uint2 bb = *(const uint2*)&SB[st][wn + ni * 8 + lg][2 * lt];
                bf[ni][0] = bb.x; bf[ni][1] = bb.y;
            }
#pragma unroll
            for (int mi = 0; mi < 2; mi++)
#pragma unroll
                for (int ni = 0; ni < 4; ni++) mma16(acc[mi][ni], af[mi], bf[ni]);
        }

        if (more) {
            SB[st ^ 1][bn_][slot]     = __byte_perm(x0, x1, 0x5410);
            SB[st ^ 1][bn_ + 1][slot] = __byte_perm(x0, x1, 0x7632);
            asm volatile("cp.async.wait_group 0;" ::: "memory");
        }
        __syncthreads();
    }

#pragma unroll
    for (int mi = 0; mi < 2; mi++) {
        int r0 = q0 + wm + mi * 16 + lg;
        float iv0 = 1.0f / g_rowsum[bh * Sq + r0];
        float iv1 = 1.0f / g_rowsum[bh * Sq + r0 + 8];
#pragma unroll
        for (int ni = 0; ni < 4; ni++) {
            int c0 = wn + ni * 8 + 2 * lt;
            size_t base0 = ((size_t)b * Sq + r0) * DMq + h * DEPTHq + c0;
            size_t base1 = ((size_t)b * Sq + r0 + 8) * DMq + h * DEPTHq + c0;
            *reinterpret_cast<uint32_t*>(&g_Zh[base0]) =
                ph2(acc[mi][ni][0] * iv0, acc[mi][ni][1] * iv0);
            *reinterpret_cast<uint32_t*>(&g_Zh[base1]) =
                ph2(acc[mi][ni][2] * iv1, acc[mi][ni][3] * iv1);
        }
    }
}

// ============================================================
// Kernel 6: out (R13 design, unchanged)
// ============================================================
__global__ void __launch_bounds__(256)
out_gemm_v2(const float* __restrict__ bo, float* __restrict__ out) {
    extern __shared__ char dsm[];
    const uint32_t sa = smem_u32(dsm);
    const uint32_t sb = sa + 2 * PSTG;

    const int m0 = blockIdx.y * 128;
    const int n0 = blockIdx.x * 128;
    const int tid = threadIdx.x;
    const int wid = tid >> 5, lane = tid & 31;
    const int wm = (wid >> 2) * 64, wn = (wid & 3) * 32;
    const int lg = lane >> 2, lt = lane & 3;

    const int crow = tid >> 3;
    const int ccc = tid & 7;

    float acc[4][4][4];
#pragma unroll
    for (int i = 0; i < 4; i++)
#pragma unroll
        for (int j = 0; j < 4; j++)
#pragma unroll
            for (int r = 0; r < 4; r++) acc[i][j][r] = 0.f;

    {
#pragma unroll
        for (int i = 0; i < 4; i++) {
            int row = crow + i * 32;
            cp16(sa + row * PROWB + ccc * 16, g_Zh + (size_t)(m0 + row) * DMq + ccc * 8);
            cp16(sb + row * PROWB + ccc * 16, g_Woth + (size_t)(n0 + row) * DMq + ccc * 8);
        }
        asm volatile("cp.async.commit_group;" ::: "memory");
        asm volatile("cp.async.wait_group 0;" ::: "memory");
    }
    __syncthreads();

    const uint32_t aAddrBase = (uint32_t)(wm + (lane & 15)) * PROWB + ((lane >> 4) & 1) * 16;
    const uint32_t bAddrBase = (uint32_t)(wn + ((lane >> 4) & 1) * 8 + (lane & 7)) * PROWB +
                               ((lane >> 3) & 1) * 16;

    const int NST = DMq / 64;
    for (int s = 0; s < NST; s++) {
        const int st = s & 1;
        const bool more = (s + 1 < NST);
        if (more) {
            int k0 = (s + 1) * 64;
#pragma unroll
            for (int i = 0; i < 4; i++) {
                int row = crow + i * 32;
                cp16(sa + (st ^ 1) * PSTG + row * PROWB + ccc * 16,
                     g_Zh + (size_t)(m0 + row) * DMq + k0 + ccc * 8);
                cp16(sb + (st ^ 1) * PSTG + row * PROWB + ccc * 16,
                     g_Woth + (size_t)(n0 + row) * DMq + k0 + ccc * 8);
            }
            asm volatile("cp.async.commit_group;" ::: "memory");
        }
        const uint32_t sas = sa + st * PSTG;
        const uint32_t sbs = sb + st * PSTG;
#pragma unroll
        for (int c = 0; c < 4; c++) {
            const uint32_t coff = c * 32;
            uint32_t bf[4][2];
#pragma unroll
            for (int np = 0; np < 2; np++) {
                uint32_t r4[4];
                ldsm4(r4, sbs + bAddrBase + np * 16 * PROWB + coff);
                bf[2 * np][0] = r4[0];
                bf[2 * np][1] = r4[1];
                bf[2 * np + 1][0] = r4[2];
                bf[2 * np + 1][1] = r4[3];
            }
#pragma unroll
            for (int mi = 0; mi < 4; mi++) {
                uint32_t af[4];
                ldsm4(af, sas + aAddrBase + mi * 16 * PROWB + coff);
#pragma unroll
                for (int ni = 0; ni < 4; ni++) mma16(acc[mi][ni], af, bf[ni]);
            }
        }
        if (more) asm volatile("cp.async.wait_group 0;" ::: "memory");
        __syncthreads();
    }

#pragma unroll
    for (int mi = 0; mi < 4; mi++) {
        int r0 = m0 + wm + mi * 16 + lg;
#pragma unroll
        for (int ni = 0; ni < 4; ni++) {
            int c0 = n0 + wn + ni * 8 + 2 * lt;
            float bv0 = bo[c0], bv1 = bo[c0 + 1];
            *reinterpret_cast<float2*>(&out[(size_t)r0 * DMq + c0]) =
                make_float2(acc[mi][ni][0] + bv0, acc[mi][ni][1] + bv1);
            *reinterpret_cast<float2*>(&out[(size_t)(r0 + 8) * DMq + c0]) =
                make_float2(acc[mi][ni][2] + bv0, acc[mi][ni][3] + bv1);
        }
    }
}

// ============================================================
// Launch
// ============================================================
extern "C" void kernel_launch(void* const* d_in, const int* in_sizes, int n_in,
                              void* d_out, int out_size) {
    const float* emb = (const float*)d_in[0];
    const float* pe  = (const float*)d_in[1];
    const float* Wq  = (const float*)d_in[2];
    const float* bq  = (const float*)d_in[3];
    const float* Wk  = (const float*)d_in[4];
    const float* bk  = (const float*)d_in[5];
    const float* Wv  = (const float*)d_in[6];
    const float* bv  = (const float*)d_in[7];
    const float* Wo  = (const float*)d_in[8];
    const float* bo  = (const float*)d_in[9];

    float* out = (float*)d_out;

    const long long need = (long long)NTOK * DMq + (long long)BHq * Sq * Sq;
    float* attn;
    if ((long long)out_size >= need) {
        attn = out + (size_t)NTOK * DMq;
    } else {
        float* p = nullptr;
        cudaGetSymbolAddress((void**)&p, g_attn_fallback);
        attn = p;
    }

    cudaFuncSetAttribute(logits_gemm_tc,
                         cudaFuncAttributeMaxDynamicSharedMemorySize, LOG_SMEM);
    cudaFuncSetAttribute(proj_gemm_v2,
                         cudaFuncAttributeMaxDynamicSharedMemorySize, PROJ_SMEM);
    cudaFuncSetAttribute(out_gemm_v2,
                         cudaFuncAttributeMaxDynamicSharedMemorySize, PROJ_SMEM);

    {
        convert_A<<<(NROWS * DMq + 255) / 256, 256>>>(emb, pe);
    }
    {
        dim3 grid(CC / 32 + DMq / 32, DMq / 32);
        convert_W_all<<<grid, dim3(32, 8)>>>(Wq, Wk, Wv, Wo);
    }
    {
        dim3 grid(CC / 128, NROWS / 128);
        proj_gemm_v2<<<grid, 256, PROJ_SMEM>>>(bq, bk, bv);
    }
    {
        int total = NTOK * (DMq / 2);
        rearrange_kernel<<<(total + 255) / 256, 256>>>();
    }
    {
        dim3 grid(Sq / 128, Sq / 128, BHq);
        logits_gemm_tc<<<grid, 128, LOG_SMEM>>>();
    }
    {
        dim3 grid(Sq / 128, BHq);
        zv_fused_tc<<<grid, 256>>>(attn);
    }
    {
        dim3 grid(DMq / 128, NTOK / 128);
        out_gemm_v2<<<grid, 256, PROJ_SMEM>>>(bo, out);
    }
}